// round 12
// baseline (speedup 1.0000x reference)
#include <cuda_runtime.h>
#include <cstdint>

// y2[a,d,z] = sum_c ( sum_b x1[a,b,z]*x0[b,c,z] ) * x2[c,d,z]
// All tensors (32,32,32768) fp32 row-major, z contiguous. Lane = one f32x2 z-pair.
// R12 = R11 block shape (128 thr / 4 warps, 8a x 8c warp tile, y1 64KB smem,
// 2 blocks/SM) + R10's av double-buffer. Both global streams now use the
// compile-time distance-1 double-buffer: av (x1, DRAM-fresh every step, the
// last unprefetched stall) and bv/xv (x0/x2, L2-shared across a-group blocks).

#define ZH   16384          // z-pairs (f32x2)
#define SDIM 32

using u64 = unsigned long long;

__device__ __forceinline__ u64 ffma2(u64 a, u64 b, u64 c) {
    u64 d;
    asm("fma.rn.f32x2 %0, %1, %2, %3;" : "=l"(d) : "l"(a), "l"(b), "l"(c));
    return d;
}

__global__ void __launch_bounds__(128, 2)
einnet_fused8_kernel(const u64* __restrict__ x0,
                     const u64* __restrict__ x1,
                     const u64* __restrict__ x2,
                     u64* __restrict__ out)
{
    // y1 tile: [a(8)][c(32)][lane(32)] u64 = 64KB
    extern __shared__ u64 y1s[];

    const int lane = threadIdx.x & 31;
    const int w    = threadIdx.x >> 5;            // 0..3
    const int cg   = w * 8;                       // c/d stripe base
    const int abas = blockIdx.x * 8;              // a-group base (0,8,16,24)
    const int p    = blockIdx.y * 32 + lane;      // global z-pair

    u64 acc[8][8];
    #pragma unroll
    for (int i = 0; i < 8; i++)
        #pragma unroll
        for (int j = 0; j < 8; j++) acc[i][j] = 0ull;

    // ---------------- Pass 1: y1[a,c] = sum_b x1[a,b] * x0[b,c] ----------------
    const u64* __restrict__ Ap = x1 + (size_t)(abas * SDIM) * ZH + p;
    const u64* __restrict__ Bp = x0 + (size_t)cg * ZH + p;

    u64 av[2][8], bv[2][8];
    #pragma unroll
    for (int i = 0; i < 8; i++) av[0][i] = Ap[(size_t)(i * SDIM) * ZH];
    #pragma unroll
    for (int j = 0; j < 8; j++) bv[0][j] = Bp[(size_t)j * ZH];

    #pragma unroll
    for (int b = 0; b < SDIM; b++) {
        const int cur = b & 1;           // compile-time after full unroll
        if (b + 1 < SDIM) {              // compile-time guard
            #pragma unroll
            for (int i = 0; i < 8; i++)
                av[cur ^ 1][i] = Ap[(size_t)(i * SDIM + b + 1) * ZH];
            #pragma unroll
            for (int j = 0; j < 8; j++)
                bv[cur ^ 1][j] = Bp[(size_t)((b + 1) * SDIM + j) * ZH];
        }

        #pragma unroll
        for (int i = 0; i < 8; i++)
            #pragma unroll
            for (int j = 0; j < 8; j++)
                acc[i][j] = ffma2(av[cur][i], bv[cur][j], acc[i][j]);
    }

    // store y1 stripe (conflict-free: lane-consecutive 8B)
    #pragma unroll
    for (int i = 0; i < 8; i++)
        #pragma unroll
        for (int j = 0; j < 8; j++)
            y1s[(i * SDIM + cg + j) * 32 + lane] = acc[i][j];
    __syncthreads();

    // ---------------- Pass 2: y2[a,d] = sum_c y1[a,c] * x2[c,d] ----------------
    #pragma unroll
    for (int i = 0; i < 8; i++)
        #pragma unroll
        for (int j = 0; j < 8; j++) acc[i][j] = 0ull;

    const u64* __restrict__ Cp = x2 + (size_t)cg * ZH + p;

    u64 xv[2][8];
    #pragma unroll
    for (int j = 0; j < 8; j++) xv[0][j] = Cp[(size_t)j * ZH];

    #pragma unroll
    for (int c = 0; c < SDIM; c++) {
        const int cur = c & 1;
        if (c + 1 < SDIM) {
            #pragma unroll
            for (int j = 0; j < 8; j++)
                xv[cur ^ 1][j] = Cp[(size_t)((c + 1) * SDIM + j) * ZH];
        }

        u64 yv[8];
        #pragma unroll
        for (int i = 0; i < 8; i++)
            yv[i] = y1s[(i * SDIM + c) * 32 + lane];   // smem, 29cyc, covered

        #pragma unroll
        for (int i = 0; i < 8; i++)
            #pragma unroll
            for (int j = 0; j < 8; j++)
                acc[i][j] = ffma2(yv[i], xv[cur][j], acc[i][j]);
    }

    u64* __restrict__ Op = out + (size_t)(abas * SDIM + cg) * ZH + p;
    #pragma unroll
    for (int i = 0; i < 8; i++)
        #pragma unroll
        for (int j = 0; j < 8; j++)
            Op[(size_t)(i * SDIM + j) * ZH] = acc[i][j];
}

extern "C" void kernel_launch(void* const* d_in, const int* in_sizes, int n_in,
                              void* d_out, int out_size)
{
    (void)in_sizes; (void)n_in; (void)out_size;
    const u64* x0 = (const u64*)d_in[0];   // (b, c, Z)
    const u64* x1 = (const u64*)d_in[1];   // (a, b, Z)
    const u64* x2 = (const u64*)d_in[2];   // (c, d, Z)
    u64* out = (u64*)d_out;

    constexpr int SMEM_BYTES = 8 * SDIM * 32 * 8;   // 65536 = 64KB
    cudaFuncSetAttribute(einnet_fused8_kernel,
                         cudaFuncAttributeMaxDynamicSharedMemorySize, SMEM_BYTES);

    // z-tile slow dim: the 4 a-group blocks of one z-tile are co-resident
    // (2 per SM) and share x0/x2 slices in L2.
    dim3 grid(4, ZH / 32);
    einnet_fused8_kernel<<<grid, 128, SMEM_BYTES>>>(x0, x1, x2, out);
}

// round 13
// speedup vs baseline: 1.0034x; 1.0034x over previous
#include <cuda_runtime.h>
#include <cstdint>

// y2[a,d,z] = sum_c ( sum_b x1[a,b,z]*x0[b,c,z] ) * x2[c,d,z]
// All tensors (32,32,32768) fp32 row-major, z contiguous. Lane = one f32x2 z-pair.
// R13 = R11 base (128 thr / 4 warps, 8a x 8c warp tile, y1 64KB smem,
// 2 blocks/SM, compile-time distance-1 double-buffer on bv/xv, av load-at-use)
// + NEW: zero-register prefetch.global.L2 at DISTANCE 2 for the DRAM streams.
// Theory: distance-1 register lead (~357cyc) < DRAM latency + L1tex queue
// (~500-700cyc); L2 prefetch 2 steps ahead converts the consuming loads into
// L2 hits (~250cyc), which distance-1 covers. av prefetch from warp 0 only
// (all 4 warps share av addresses).

#define ZH   16384          // z-pairs (f32x2)
#define SDIM 32

using u64 = unsigned long long;

__device__ __forceinline__ u64 ffma2(u64 a, u64 b, u64 c) {
    u64 d;
    asm("fma.rn.f32x2 %0, %1, %2, %3;" : "=l"(d) : "l"(a), "l"(b), "l"(c));
    return d;
}

__device__ __forceinline__ void pf_l2(const u64* ptr) {
    asm volatile("prefetch.global.L2 [%0];" :: "l"(ptr));
}

__global__ void __launch_bounds__(128, 2)
einnet_fused9_kernel(const u64* __restrict__ x0,
                     const u64* __restrict__ x1,
                     const u64* __restrict__ x2,
                     u64* __restrict__ out)
{
    // y1 tile: [a(8)][c(32)][lane(32)] u64 = 64KB
    extern __shared__ u64 y1s[];

    const int lane = threadIdx.x & 31;
    const int w    = threadIdx.x >> 5;            // 0..3
    const int cg   = w * 8;                       // c/d stripe base
    const int abas = blockIdx.x * 8;              // a-group base (0,8,16,24)
    const int p    = blockIdx.y * 32 + lane;      // global z-pair

    u64 acc[8][8];
    #pragma unroll
    for (int i = 0; i < 8; i++)
        #pragma unroll
        for (int j = 0; j < 8; j++) acc[i][j] = 0ull;

    // ---------------- Pass 1: y1[a,c] = sum_b x1[a,b] * x0[b,c] ----------------
    const u64* __restrict__ Ap = x1 + (size_t)(abas * SDIM) * ZH + p;
    const u64* __restrict__ Bp = x0 + (size_t)cg * ZH + p;

    // warm L2 for the first two steps' rows
    #pragma unroll
    for (int s = 0; s < 2; s++) {
        if (w == 0) {
            #pragma unroll
            for (int i = 0; i < 8; i++) pf_l2(Ap + (size_t)(i * SDIM + s) * ZH);
        }
        #pragma unroll
        for (int j = 0; j < 8; j++) pf_l2(Bp + (size_t)(s * SDIM + j) * ZH);
    }

    u64 bv[2][8];
    #pragma unroll
    for (int j = 0; j < 8; j++) bv[0][j] = Bp[(size_t)j * ZH];

    #pragma unroll
    for (int b = 0; b < SDIM; b++) {
        const int cur = b & 1;           // compile-time after full unroll
        if (b + 1 < SDIM) {              // compile-time guard
            #pragma unroll
            for (int j = 0; j < 8; j++)
                bv[cur ^ 1][j] = Bp[(size_t)((b + 1) * SDIM + j) * ZH];
        }
        if (b + 2 < SDIM) {              // distance-2 L2 prefetch (no registers)
            if (w == 0) {
                #pragma unroll
                for (int i = 0; i < 8; i++)
                    pf_l2(Ap + (size_t)(i * SDIM + b + 2) * ZH);
            }
            #pragma unroll
            for (int j = 0; j < 8; j++)
                pf_l2(Bp + (size_t)((b + 2) * SDIM + j) * ZH);
        }

        u64 av[8];
        #pragma unroll
        for (int i = 0; i < 8; i++) av[i] = Ap[(size_t)(i * SDIM + b) * ZH];

        #pragma unroll
        for (int i = 0; i < 8; i++)
            #pragma unroll
            for (int j = 0; j < 8; j++)
                acc[i][j] = ffma2(av[i], bv[cur][j], acc[i][j]);
    }

    // store y1 stripe (conflict-free: lane-consecutive 8B)
    #pragma unroll
    for (int i = 0; i < 8; i++)
        #pragma unroll
        for (int j = 0; j < 8; j++)
            y1s[(i * SDIM + cg + j) * 32 + lane] = acc[i][j];
    __syncthreads();

    // ---------------- Pass 2: y2[a,d] = sum_c y1[a,c] * x2[c,d] ----------------
    #pragma unroll
    for (int i = 0; i < 8; i++)
        #pragma unroll
        for (int j = 0; j < 8; j++) acc[i][j] = 0ull;

    const u64* __restrict__ Cp = x2 + (size_t)cg * ZH + p;

    #pragma unroll
    for (int s = 0; s < 2; s++) {
        #pragma unroll
        for (int j = 0; j < 8; j++) pf_l2(Cp + (size_t)(s * SDIM + j) * ZH);
    }

    u64 xv[2][8];
    #pragma unroll
    for (int j = 0; j < 8; j++) xv[0][j] = Cp[(size_t)j * ZH];

    #pragma unroll
    for (int c = 0; c < SDIM; c++) {
        const int cur = c & 1;
        if (c + 1 < SDIM) {
            #pragma unroll
            for (int j = 0; j < 8; j++)
                xv[cur ^ 1][j] = Cp[(size_t)((c + 1) * SDIM + j) * ZH];
        }
        if (c + 2 < SDIM) {
            #pragma unroll
            for (int j = 0; j < 8; j++)
                pf_l2(Cp + (size_t)((c + 2) * SDIM + j) * ZH);
        }

        u64 yv[8];
        #pragma unroll
        for (int i = 0; i < 8; i++)
            yv[i] = y1s[(i * SDIM + c) * 32 + lane];   // smem, 29cyc, covered

        #pragma unroll
        for (int i = 0; i < 8; i++)
            #pragma unroll
            for (int j = 0; j < 8; j++)
                acc[i][j] = ffma2(yv[i], xv[cur][j], acc[i][j]);
    }

    u64* __restrict__ Op = out + (size_t)(abas * SDIM + cg) * ZH + p;
    #pragma unroll
    for (int i = 0; i < 8; i++)
        #pragma unroll
        for (int j = 0; j < 8; j++)
            Op[(size_t)(i * SDIM + j) * ZH] = acc[i][j];
}

extern "C" void kernel_launch(void* const* d_in, const int* in_sizes, int n_in,
                              void* d_out, int out_size)
{
    (void)in_sizes; (void)n_in; (void)out_size;
    const u64* x0 = (const u64*)d_in[0];   // (b, c, Z)
    const u64* x1 = (const u64*)d_in[1];   // (a, b, Z)
    const u64* x2 = (const u64*)d_in[2];   // (c, d, Z)
    u64* out = (u64*)d_out;

    constexpr int SMEM_BYTES = 8 * SDIM * 32 * 8;   // 65536 = 64KB
    cudaFuncSetAttribute(einnet_fused9_kernel,
                         cudaFuncAttributeMaxDynamicSharedMemorySize, SMEM_BYTES);

    // z-tile slow dim: the 4 a-group blocks of one z-tile are co-resident
    // (2 per SM) and share x0/x2 slices in L2.
    dim3 grid(4, ZH / 32);
    einnet_fused9_kernel<<<grid, 128, SMEM_BYTES>>>(x0, x1, x2, out);
}

// round 14
// speedup vs baseline: 1.0722x; 1.0686x over previous
#include <cuda_runtime.h>
#include <cstdint>

// y2[a,d,z] = sum_c ( sum_b x1[a,b,z]*x0[b,c,z] ) * x2[c,d,z]
// All tensors (32,32,32768) fp32 row-major, z contiguous. Lane = one f32x2 z-pair.
// R14 = R11 base (128 thr / 4 warps, 8a x 8c warp tile, y1 64KB smem,
// 2 blocks/SM, compile-time distance-1 double-buffer on bv/xv)
// + NEW: per-warp / per-block ROTATED reduction order. Warp w of block bx
// starts the b-loop (and c-loop) at row chunk ((w+bx)&3)*8. This decorrelates
// the miss streams: the 4 warps of a block (identical av addresses) and the
// 4 a-group blocks of a z-tile (identical bv addresses) previously all
// stalled on the SAME line fill each step -> ~1 unique DRAM line in flight.
// Rotation puts 4x more unique lines in flight; L1/L2 fills convert the
// followers to hits. fp32 sum reorder only (rel_err ~1e-7 << 1e-3).

#define ZH   16384          // z-pairs (f32x2)
#define SDIM 32

using u64 = unsigned long long;

__device__ __forceinline__ u64 ffma2(u64 a, u64 b, u64 c) {
    u64 d;
    asm("fma.rn.f32x2 %0, %1, %2, %3;" : "=l"(d) : "l"(a), "l"(b), "l"(c));
    return d;
}

__global__ void __launch_bounds__(128, 2)
einnet_fused10_kernel(const u64* __restrict__ x0,
                      const u64* __restrict__ x1,
                      const u64* __restrict__ x2,
                      u64* __restrict__ out)
{
    // y1 tile: [a(8)][c(32)][lane(32)] u64 = 64KB
    extern __shared__ u64 y1s[];

    const int lane = threadIdx.x & 31;
    const int w    = threadIdx.x >> 5;            // 0..3
    const int cg   = w * 8;                       // c/d stripe base (output cols)
    const int abas = blockIdx.x * 8;              // a-group base (0,8,16,24)
    const int p    = blockIdx.y * 32 + lane;      // global z-pair
    const int rot  = (w + blockIdx.x) & 3;        // reduction-order rotation

    u64 acc[8][8];
    #pragma unroll
    for (int i = 0; i < 8; i++)
        #pragma unroll
        for (int j = 0; j < 8; j++) acc[i][j] = 0ull;

    // ---------------- Pass 1: y1[a,c] = sum_b x1[a,b] * x0[b,c] ----------------
    const u64* __restrict__ Ap = x1 + (size_t)(abas * SDIM) * ZH + p;
    const u64* __restrict__ Bp = x0 + (size_t)cg * ZH + p;

    u64 bv[2][8];
    {   // initial load: chunk `rot`, step 0  (row = rot*8)
        const u64* Br = Bp + (size_t)(rot * 8) * SDIM * ZH;
        #pragma unroll
        for (int j = 0; j < 8; j++) bv[0][j] = Br[(size_t)j * ZH];
    }

    for (int kk = 0; kk < 4; kk++) {              // 4 chunks (runtime rot base)
        const int ch  = (rot + kk) & 3;
        const int chn = (rot + kk + 1) & 3;
        const u64* __restrict__ Ar  = Ap + (size_t)(ch  * 8) * ZH;         // av rows
        const u64* __restrict__ Br  = Bp + (size_t)(ch  * 8) * SDIM * ZH;  // bv rows
        const u64* __restrict__ Brn = Bp + (size_t)(chn * 8) * SDIM * ZH;  // next chunk

        #pragma unroll
        for (int s = 0; s < 8; s++) {             // compile-time steps
            const int cur = s & 1;
            if (s + 1 < 8) {
                #pragma unroll
                for (int j = 0; j < 8; j++)
                    bv[cur ^ 1][j] = Br[(size_t)((s + 1) * SDIM + j) * ZH];
            } else if (kk + 1 < 4) {
                #pragma unroll
                for (int j = 0; j < 8; j++)
                    bv[cur ^ 1][j] = Brn[(size_t)j * ZH];
            }

            u64 av[8];
            #pragma unroll
            for (int i = 0; i < 8; i++) av[i] = Ar[(size_t)(i * SDIM + s) * ZH];

            #pragma unroll
            for (int i = 0; i < 8; i++)
                #pragma unroll
                for (int j = 0; j < 8; j++)
                    acc[i][j] = ffma2(av[i], bv[cur][j], acc[i][j]);
        }
    }

    // store y1 stripe (conflict-free: lane-consecutive 8B)
    #pragma unroll
    for (int i = 0; i < 8; i++)
        #pragma unroll
        for (int j = 0; j < 8; j++)
            y1s[(i * SDIM + cg + j) * 32 + lane] = acc[i][j];
    __syncthreads();

    // ---------------- Pass 2: y2[a,d] = sum_c y1[a,c] * x2[c,d] ----------------
    #pragma unroll
    for (int i = 0; i < 8; i++)
        #pragma unroll
        for (int j = 0; j < 8; j++) acc[i][j] = 0ull;

    const u64* __restrict__ Cp = x2 + (size_t)cg * ZH + p;

    u64 xv[2][8];
    {
        const u64* Cr = Cp + (size_t)(rot * 8) * SDIM * ZH;
        #pragma unroll
        for (int j = 0; j < 8; j++) xv[0][j] = Cr[(size_t)j * ZH];
    }

    for (int kk = 0; kk < 4; kk++) {
        const int ch  = (rot + kk) & 3;
        const int chn = (rot + kk + 1) & 3;
        const u64* __restrict__ Cr  = Cp + (size_t)(ch  * 8) * SDIM * ZH;
        const u64* __restrict__ Crn = Cp + (size_t)(chn * 8) * SDIM * ZH;
        const u64* __restrict__ Yr  = y1s + (size_t)(ch * 8) * 32;   // y1 rows (c dim)

        #pragma unroll
        for (int s = 0; s < 8; s++) {
            const int cur = s & 1;
            if (s + 1 < 8) {
                #pragma unroll
                for (int j = 0; j < 8; j++)
                    xv[cur ^ 1][j] = Cr[(size_t)((s + 1) * SDIM + j) * ZH];
            } else if (kk + 1 < 4) {
                #pragma unroll
                for (int j = 0; j < 8; j++)
                    xv[cur ^ 1][j] = Crn[(size_t)j * ZH];
            }

            u64 yv[8];
            #pragma unroll
            for (int i = 0; i < 8; i++)
                yv[i] = Yr[((size_t)i * SDIM + s) * 32 + lane];   // smem, conflict-free

            #pragma unroll
            for (int i = 0; i < 8; i++)
                #pragma unroll
                for (int j = 0; j < 8; j++)
                    acc[i][j] = ffma2(yv[i], xv[cur][j], acc[i][j]);
        }
    }

    u64* __restrict__ Op = out + (size_t)(abas * SDIM + cg) * ZH + p;
    #pragma unroll
    for (int i = 0; i < 8; i++)
        #pragma unroll
        for (int j = 0; j < 8; j++)
            Op[(size_t)(i * SDIM + j) * ZH] = acc[i][j];
}

extern "C" void kernel_launch(void* const* d_in, const int* in_sizes, int n_in,
                              void* d_out, int out_size)
{
    (void)in_sizes; (void)n_in; (void)out_size;
    const u64* x0 = (const u64*)d_in[0];   // (b, c, Z)
    const u64* x1 = (const u64*)d_in[1];   // (a, b, Z)
    const u64* x2 = (const u64*)d_in[2];   // (c, d, Z)
    u64* out = (u64*)d_out;

    constexpr int SMEM_BYTES = 8 * SDIM * 32 * 8;   // 65536 = 64KB
    cudaFuncSetAttribute(einnet_fused10_kernel,
                         cudaFuncAttributeMaxDynamicSharedMemorySize, SMEM_BYTES);

    // z-tile slow dim: the 4 a-group blocks of one z-tile are co-resident
    // (2 per SM) and share x0/x2 slices in L2.
    dim3 grid(4, ZH / 32);
    einnet_fused10_kernel<<<grid, 128, SMEM_BYTES>>>(x0, x1, x2, out);
}